// round 2
// baseline (speedup 1.0000x reference)
#include <cuda_runtime.h>
#include <math.h>

// Problem constants
#define B_  4
#define T_  2048
#define C_  1024
#define NH_ 16
#define HD_ 64
#define BH_ (B_*NH_)     // 64
#define M_  (B_*T_)      // 8192

// Scratch (allocation-free: __device__ globals)
__device__ float g_q[BH_*T_*HD_];   // [B,NH,T,HD]
__device__ float g_k[BH_*T_*HD_];
__device__ float g_v[BH_*T_*HD_];
__device__ float g_y[M_*C_];        // [B,T,C] attention output

// ---------------------------------------------------------------------------
// SGEMM: C = A @ W + bias.  A [M,K] row-major, W [K,N] row-major.
// MODE 0: A = x, scatter into g_q/g_k/g_v ([B,NH,T,HD] layout), bias fused.
// MODE 1: A = g_y, plain row-major output to C with bias.
// 128x128x16 tile, 256 threads, 8x8 per-thread micro-tile.
// ---------------------------------------------------------------------------
template <int MODE>
__global__ __launch_bounds__(256) void sgemm_kernel(
    const float* __restrict__ A_in, const float* __restrict__ W,
    const float* __restrict__ bias, float* __restrict__ Cout,
    int M, int N, int K)
{
    const int BM = 128, BN = 128, BK = 16, TM = 8, TN = 8;
    __shared__ float As[BK][BM];   // transposed A tile
    __shared__ float Bs[BK][BN];

    const float* A = (MODE == 0) ? A_in : g_y;

    int tid  = threadIdx.x;
    int cRow = blockIdx.y, cCol = blockIdx.x;
    int tr = tid / 16, tc = tid % 16;        // 16x16 thread grid

    int aRow = tid / 4;            // 0..63
    int aCol = (tid % 4) * 4;      // 0,4,8,12
    int bRow = tid / 32;           // 0..7
    int bCol = (tid % 32) * 4;     // 0..124

    const float* Ablk = A + (size_t)cRow * BM * K;
    const float* Wblk = W + cCol * BN;

    float acc[TM][TN];
    #pragma unroll
    for (int i = 0; i < TM; i++)
        #pragma unroll
        for (int j = 0; j < TN; j++) acc[i][j] = 0.f;

    float regM[TM], regN[TN];

    for (int k0 = 0; k0 < K; k0 += BK) {
        #pragma unroll
        for (int i = 0; i < 2; i++) {
            int r = aRow + i * 64;
            float4 v = *reinterpret_cast<const float4*>(&Ablk[(size_t)r * K + k0 + aCol]);
            As[aCol + 0][r] = v.x;
            As[aCol + 1][r] = v.y;
            As[aCol + 2][r] = v.z;
            As[aCol + 3][r] = v.w;
        }
        #pragma unroll
        for (int i = 0; i < 2; i++) {
            int r = bRow + i * 8;
            *reinterpret_cast<float4*>(&Bs[r][bCol]) =
                *reinterpret_cast<const float4*>(&Wblk[(size_t)(k0 + r) * N + bCol]);
        }
        __syncthreads();

        #pragma unroll
        for (int k = 0; k < BK; k++) {
            #pragma unroll
            for (int i = 0; i < TM; i++) regM[i] = As[k][tr * TM + i];
            #pragma unroll
            for (int j = 0; j < TN; j++) regN[j] = Bs[k][tc * TN + j];
            #pragma unroll
            for (int i = 0; i < TM; i++)
                #pragma unroll
                for (int j = 0; j < TN; j++)
                    acc[i][j] += regM[i] * regN[j];
        }
        __syncthreads();
    }

    int mBase = cRow * BM + tr * TM;
    int nBase = cCol * BN + tc * TN;

    if (MODE == 1) {
        #pragma unroll
        for (int i = 0; i < TM; i++) {
            #pragma unroll
            for (int j = 0; j < TN; j++) {
                int n = nBase + j;
                Cout[(size_t)(mBase + i) * N + n] = acc[i][j] + bias[n];
            }
        }
    } else {
        #pragma unroll
        for (int i = 0; i < TM; i++) {
            int m = mBase + i;
            int b = m / T_, t = m % T_;
            #pragma unroll
            for (int j = 0; j < TN; j++) {
                int n = nBase + j;
                int which = n / C_;
                int c = n % C_;
                int h = c / HD_, d = c % HD_;
                float val = acc[i][j] + bias[n];
                float* dst = (which == 0) ? g_q : (which == 1) ? g_k : g_v;
                dst[(((size_t)b * NH_ + h) * T_ + t) * HD_ + d] = val;
            }
        }
    }
}

// ---------------------------------------------------------------------------
// Flash attention, fp32, causal.  64x64 tiles, HD=64.
// grid = (32, 64): x = reversed q-tile (heavy tiles first), y = b*NH + h.
// 256 threads = 8 warps; warp w owns q-rows [w*8, w*8+8); lane owns keys
// {lane, lane+32} and output dims {lane, lane+32}.
// ---------------------------------------------------------------------------
__global__ __launch_bounds__(256) void flash_kernel()
{
    extern __shared__ float sm[];
    float* Qs = sm;                  // [64][64]
    float* Ks = Qs + 64 * 64;        // [64][68]  (pad for conflict-free .128)
    float* Vs = Ks + 64 * 68;        // [64][68]
    float* Ps = Vs + 64 * 68;        // [64][64]  (8 warps x 8 rows x 64 keys)

    int bh = blockIdx.y;
    int qt = gridDim.x - 1 - blockIdx.x;    // heavy tiles launch first
    int q0 = qt * 64;
    int tid = threadIdx.x;
    int warp = tid >> 5, lane = tid & 31;

    const float* Qg = g_q + ((size_t)bh * T_ + q0) * HD_;
    const float* Kg = g_k + (size_t)bh * T_ * HD_;
    const float* Vg = g_v + (size_t)bh * T_ * HD_;

    // Load Q tile (4096 floats; 4 x float4 per thread)
    #pragma unroll
    for (int i = 0; i < 4; i++) {
        int idx = (tid + i * 256) * 4;
        int r = idx >> 6, d = idx & 63;
        *reinterpret_cast<float4*>(&Qs[r * 64 + d]) =
            *reinterpret_cast<const float4*>(&Qg[r * 64 + d]);
    }

    float m_i[8], l_i[8], Oc[8][2];
    #pragma unroll
    for (int rr = 0; rr < 8; rr++) {
        m_i[rr] = -INFINITY; l_i[rr] = 0.f; Oc[rr][0] = 0.f; Oc[rr][1] = 0.f;
    }

    __syncthreads();

    int row0 = warp * 8;
    const float scale = 0.125f;   // 1/sqrt(64)

    for (int kt = 0; kt <= qt; kt++) {
        int k0 = kt * 64;

        // Load K, V tiles
        #pragma unroll
        for (int i = 0; i < 4; i++) {
            int idx = (tid + i * 256) * 4;
            int r = idx >> 6, d = idx & 63;
            *reinterpret_cast<float4*>(&Ks[r * 68 + d]) =
                *reinterpret_cast<const float4*>(&Kg[(size_t)(k0 + r) * 64 + d]);
            *reinterpret_cast<float4*>(&Vs[r * 68 + d]) =
                *reinterpret_cast<const float4*>(&Vg[(size_t)(k0 + r) * 64 + d]);
        }
        __syncthreads();

        // S = Q K^T : rows row0..row0+7, keys {lane, lane+32}
        float s0[8], s1[8];
        #pragma unroll
        for (int rr = 0; rr < 8; rr++) { s0[rr] = 0.f; s1[rr] = 0.f; }
        #pragma unroll
        for (int d4 = 0; d4 < 16; d4++) {
            float4 kv0 = *reinterpret_cast<const float4*>(&Ks[lane * 68 + d4 * 4]);
            float4 kv1 = *reinterpret_cast<const float4*>(&Ks[(lane + 32) * 68 + d4 * 4]);
            #pragma unroll
            for (int rr = 0; rr < 8; rr++) {
                float4 qv = *reinterpret_cast<const float4*>(&Qs[(row0 + rr) * 64 + d4 * 4]);
                s0[rr] += qv.x * kv0.x + qv.y * kv0.y + qv.z * kv0.z + qv.w * kv0.w;
                s1[rr] += qv.x * kv1.x + qv.y * kv1.y + qv.z * kv1.z + qv.w * kv1.w;
            }
        }

        int key0 = k0 + lane, key1 = k0 + lane + 32;
        #pragma unroll
        for (int rr = 0; rr < 8; rr++) {
            int qidx = q0 + row0 + rr;
            float v0 = (key0 <= qidx) ? s0[rr] * scale : -INFINITY;
            float v1 = (key1 <= qidx) ? s1[rr] * scale : -INFINITY;
            float mt = fmaxf(v0, v1);
            #pragma unroll
            for (int off = 16; off > 0; off >>= 1)
                mt = fmaxf(mt, __shfl_xor_sync(0xffffffffu, mt, off));
            float mnew = fmaxf(m_i[rr], mt);
            float alpha = __expf(m_i[rr] - mnew);
            float p0 = __expf(v0 - mnew);
            float p1 = __expf(v1 - mnew);
            float rs = p0 + p1;
            #pragma unroll
            for (int off = 16; off > 0; off >>= 1)
                rs += __shfl_xor_sync(0xffffffffu, rs, off);
            l_i[rr] = l_i[rr] * alpha + rs;
            m_i[rr] = mnew;
            Oc[rr][0] *= alpha;
            Oc[rr][1] *= alpha;
            Ps[(row0 + rr) * 64 + lane]      = p0;
            Ps[(row0 + rr) * 64 + lane + 32] = p1;
        }
        __syncwarp();

        // O += P @ V  (lane owns dims lane, lane+32)
        #pragma unroll
        for (int k4 = 0; k4 < 16; k4++) {
            float va[4], vb[4];
            #pragma unroll
            for (int i = 0; i < 4; i++) {
                va[i] = Vs[(k4 * 4 + i) * 68 + lane];
                vb[i] = Vs[(k4 * 4 + i) * 68 + lane + 32];
            }
            #pragma unroll
            for (int rr = 0; rr < 8; rr++) {
                float4 p = *reinterpret_cast<const float4*>(&Ps[(row0 + rr) * 64 + k4 * 4]);
                Oc[rr][0] += p.x * va[0] + p.y * va[1] + p.z * va[2] + p.w * va[3];
                Oc[rr][1] += p.x * vb[0] + p.y * vb[1] + p.z * vb[2] + p.w * vb[3];
            }
        }
        __syncthreads();   // before overwriting K/V tiles
    }

    // Normalize and write y in [B,T,C] layout
    int b = bh / NH_, h = bh % NH_;
    #pragma unroll
    for (int rr = 0; rr < 8; rr++) {
        int t = q0 + row0 + rr;
        float inv = 1.f / l_i[rr];
        float* yrow = g_y + ((size_t)b * T_ + t) * C_ + h * HD_;
        yrow[lane]      = Oc[rr][0] * inv;
        yrow[lane + 32] = Oc[rr][1] * inv;
    }
}

// ---------------------------------------------------------------------------
extern "C" void kernel_launch(void* const* d_in, const int* in_sizes, int n_in,
                              void* d_out, int out_size)
{
    const float* x     = (const float*)d_in[0];
    const float* Wqkv  = (const float*)d_in[1];
    const float* bqkv  = (const float*)d_in[2];
    const float* Wproj = (const float*)d_in[3];
    const float* bproj = (const float*)d_in[4];
    float* out = (float*)d_out;

    // 1) QKV GEMM: [8192,1024] @ [1024,3072], scatter into g_q/g_k/g_v
    {
        dim3 grid(3072 / 128, 8192 / 128);
        sgemm_kernel<0><<<grid, 256>>>(x, Wqkv, bqkv, nullptr, M_, 3 * C_, C_);
    }

    // 2) Flash attention (causal), writes g_y
    {
        const int smem = (64 * 64 + 2 * 64 * 68 + 64 * 64) * (int)sizeof(float); // 67584
        cudaFuncSetAttribute(flash_kernel, cudaFuncAttributeMaxDynamicSharedMemorySize, smem);
        flash_kernel<<<dim3(32, 64), 256, smem>>>();
    }

    // 3) Projection GEMM: g_y @ [1024,1024] + bproj -> out
    {
        dim3 grid(1024 / 128, 8192 / 128);
        sgemm_kernel<1><<<grid, 256>>>(nullptr, Wproj, bproj, out, M_, C_, C_);
    }
}

// round 3
// speedup vs baseline: 1.5957x; 1.5957x over previous
#include <cuda_runtime.h>
#include <cuda_bf16.h>
#include <math.h>
#include <stdint.h>

// Problem constants
#define B_  4
#define T_  2048
#define C_  1024
#define NH_ 16
#define HD_ 64
#define BH_ (B_*NH_)     // 64
#define M_  (B_*T_)      // 8192

// Scratch (allocation-free: __device__ globals)
__device__ float g_q[BH_*T_*HD_];   // [B,NH,T,HD]
__device__ float g_k[BH_*T_*HD_];
__device__ float g_v[BH_*T_*HD_];
__device__ float g_y[M_*C_];        // [B,T,C] attention output

__device__ __forceinline__ uint32_t smem_u32(const void* p) {
    return (uint32_t)__cvta_generic_to_shared(p);
}

#define LDSM4(R, ptr)                                                          \
    asm volatile("ldmatrix.sync.aligned.m8n8.x4.shared.b16 {%0,%1,%2,%3}, [%4];" \
                 : "=r"((R)[0]), "=r"((R)[1]), "=r"((R)[2]), "=r"((R)[3])      \
                 : "r"(smem_u32(ptr)))

#define LDSM4T(R, ptr)                                                         \
    asm volatile("ldmatrix.sync.aligned.m8n8.x4.trans.shared.b16 {%0,%1,%2,%3}, [%4];" \
                 : "=r"((R)[0]), "=r"((R)[1]), "=r"((R)[2]), "=r"((R)[3])      \
                 : "r"(smem_u32(ptr)))

#define MMA16816(D, A, b0, b1)                                                 \
    asm volatile("mma.sync.aligned.m16n8k16.row.col.f32.bf16.bf16.f32 "        \
                 "{%0,%1,%2,%3}, {%4,%5,%6,%7}, {%8,%9}, {%0,%1,%2,%3};"       \
                 : "+f"((D)[0]), "+f"((D)[1]), "+f"((D)[2]), "+f"((D)[3])      \
                 : "r"((A)[0]), "r"((A)[1]), "r"((A)[2]), "r"((A)[3]),         \
                   "r"(b0), "r"(b1))

__device__ __forceinline__ void split_bf16(float x, __nv_bfloat16& h, __nv_bfloat16& l) {
    h = __float2bfloat16(x);
    l = __float2bfloat16(x - __bfloat162float(h));
}

// ---------------------------------------------------------------------------
// GEMM via 3x bf16-split tensor-core mma: C = A @ W + bias (fp32 in/out).
// Block tile 128x128, BK=32, 256 threads = 8 warps (4m x 2n), warp tile 32x64.
// MODE 0: A = x, scatter result into g_q/g_k/g_v ([B,NH,T,HD]).
// MODE 1: A = g_y, row-major output.
// ---------------------------------------------------------------------------
template <int MODE>
__global__ __launch_bounds__(256) void gemm_bf16x3(
    const float* __restrict__ A_in, const float* __restrict__ W,
    const float* __restrict__ bias, float* __restrict__ Cout,
    int M, int N, int K)
{
    constexpr int LDA = 40;    // A smem stride (32 + 8 pad), bf16 elems
    constexpr int LDB = 136;   // B smem stride (128 + 8 pad), bf16 elems
    __shared__ __nv_bfloat16 Ah[128 * LDA], Al[128 * LDA];  // [m][k]
    __shared__ __nv_bfloat16 Bh[32 * LDB],  Bl[32 * LDB];   // [k][n]

    const float* A = (MODE == 0) ? A_in : g_y;

    int tid  = threadIdx.x;
    int lane = tid & 31, warp = tid >> 5;
    int cRow = blockIdx.y, cCol = blockIdx.x;
    int warpM = warp & 3, warpN = warp >> 2;
    int mr0 = warpM * 32;      // warp m-offset within block tile
    int n0w = warpN * 64;      // warp n-offset within block tile

    float acc[2][8][4];
    #pragma unroll
    for (int i = 0; i < 2; i++)
        #pragma unroll
        for (int j = 0; j < 8; j++)
            #pragma unroll
            for (int q = 0; q < 4; q++) acc[i][j][q] = 0.f;

    const float* Ab = A + (size_t)cRow * 128 * K;
    const float* Wb = W + cCol * 128;

    for (int k0 = 0; k0 < K; k0 += 32) {
        // --- load + split A tile [128][32] ---
        #pragma unroll
        for (int p = 0; p < 4; p++) {
            int idx = p * 256 + tid;
            int r = idx >> 3;
            int c4 = (idx & 7) << 2;
            float4 v = *reinterpret_cast<const float4*>(Ab + (size_t)r * K + k0 + c4);
            __nv_bfloat16 h0, l0, h1, l1, h2, l2, h3, l3;
            split_bf16(v.x, h0, l0); split_bf16(v.y, h1, l1);
            split_bf16(v.z, h2, l2); split_bf16(v.w, h3, l3);
            __nv_bfloat16* ah = &Ah[r * LDA + c4];
            __nv_bfloat16* al = &Al[r * LDA + c4];
            *reinterpret_cast<__nv_bfloat162*>(ah)     = __halves2bfloat162(h0, h1);
            *reinterpret_cast<__nv_bfloat162*>(ah + 2) = __halves2bfloat162(h2, h3);
            *reinterpret_cast<__nv_bfloat162*>(al)     = __halves2bfloat162(l0, l1);
            *reinterpret_cast<__nv_bfloat162*>(al + 2) = __halves2bfloat162(l2, l3);
        }
        // --- load + split W tile [32][128] ---
        #pragma unroll
        for (int p = 0; p < 4; p++) {
            int idx = p * 256 + tid;
            int kr = idx >> 5;
            int n4 = (idx & 31) << 2;
            float4 v = *reinterpret_cast<const float4*>(Wb + (size_t)(k0 + kr) * N + n4);
            __nv_bfloat16 h0, l0, h1, l1, h2, l2, h3, l3;
            split_bf16(v.x, h0, l0); split_bf16(v.y, h1, l1);
            split_bf16(v.z, h2, l2); split_bf16(v.w, h3, l3);
            __nv_bfloat16* bh = &Bh[kr * LDB + n4];
            __nv_bfloat16* bl = &Bl[kr * LDB + n4];
            *reinterpret_cast<__nv_bfloat162*>(bh)     = __halves2bfloat162(h0, h1);
            *reinterpret_cast<__nv_bfloat162*>(bh + 2) = __halves2bfloat162(h2, h3);
            *reinterpret_cast<__nv_bfloat162*>(bl)     = __halves2bfloat162(l0, l1);
            *reinterpret_cast<__nv_bfloat162*>(bl + 2) = __halves2bfloat162(l2, l3);
        }
        __syncthreads();

        // --- compute: 2 k16 steps ---
        #pragma unroll
        for (int k16 = 0; k16 < 2; k16++) {
            int kk = k16 * 16;
            uint32_t ahf[2][4], alf[2][4], bhf[4][4], blf[4][4];

            #pragma unroll
            for (int mi = 0; mi < 2; mi++) {
                int off = (mr0 + mi * 16 + (lane & 15)) * LDA + kk + ((lane >> 4) << 3);
                LDSM4(ahf[mi], &Ah[off]);
                LDSM4(alf[mi], &Al[off]);
            }
            #pragma unroll
            for (int g = 0; g < 4; g++) {
                int r = kk + ((lane & 16) >> 1) + (lane & 7);
                int c = n0w + g * 16 + (lane & 8);
                int off = r * LDB + c;
                LDSM4T(bhf[g], &Bh[off]);
                LDSM4T(blf[g], &Bl[off]);
            }

            #pragma unroll
            for (int mi = 0; mi < 2; mi++) {
                #pragma unroll
                for (int nj = 0; nj < 8; nj++) {
                    int g = nj >> 1, h = nj & 1;
                    uint32_t b0h = h ? bhf[g][1] : bhf[g][0];
                    uint32_t b1h = h ? bhf[g][3] : bhf[g][2];
                    uint32_t b0l = h ? blf[g][1] : blf[g][0];
                    uint32_t b1l = h ? blf[g][3] : blf[g][2];
                    MMA16816(acc[mi][nj], ahf[mi], b0h, b1h);   // hi*hi
                    MMA16816(acc[mi][nj], ahf[mi], b0l, b1l);   // hi*lo
                    MMA16816(acc[mi][nj], alf[mi], b0h, b1h);   // lo*hi
                }
            }
        }
        __syncthreads();
    }

    // --- epilogue ---
    int rbase = cRow * 128 + mr0 + (lane >> 2);
    int cbase = cCol * 128 + n0w + ((lane & 3) << 1);

    #pragma unroll
    for (int mi = 0; mi < 2; mi++) {
        #pragma unroll
        for (int nj = 0; nj < 8; nj++) {
            int m0 = rbase + mi * 16;
            int n  = cbase + nj * 8;
            float bv0 = bias[n], bv1 = bias[n + 1];
            float v00 = acc[mi][nj][0] + bv0, v01 = acc[mi][nj][1] + bv1;
            float v10 = acc[mi][nj][2] + bv0, v11 = acc[mi][nj][3] + bv1;
            if (MODE == 1) {
                *reinterpret_cast<float2*>(&Cout[(size_t)m0 * N + n])       = make_float2(v00, v01);
                *reinterpret_cast<float2*>(&Cout[(size_t)(m0 + 8) * N + n]) = make_float2(v10, v11);
            } else {
                int which = n / C_;
                int c = n - which * C_;
                int h = c >> 6, d = c & 63;
                float* dst = (which == 0) ? g_q : (which == 1) ? g_k : g_v;
                int b0i = m0 >> 11, t0 = m0 & 2047;
                int b1i = (m0 + 8) >> 11, t1 = (m0 + 8) & 2047;
                *reinterpret_cast<float2*>(&dst[(((size_t)b0i * NH_ + h) * T_ + t0) * HD_ + d]) = make_float2(v00, v01);
                *reinterpret_cast<float2*>(&dst[(((size_t)b1i * NH_ + h) * T_ + t1) * HD_ + d]) = make_float2(v10, v11);
            }
        }
    }
}

// ---------------------------------------------------------------------------
// Flash attention, fp32, causal.  64x64 tiles, HD=64. (unchanged from R2)
// ---------------------------------------------------------------------------
__global__ __launch_bounds__(256) void flash_kernel()
{
    extern __shared__ float sm[];
    float* Qs = sm;                  // [64][64]
    float* Ks = Qs + 64 * 64;        // [64][68]
    float* Vs = Ks + 64 * 68;        // [64][68]
    float* Ps = Vs + 64 * 68;        // [64][64]

    int bh = blockIdx.y;
    int qt = gridDim.x - 1 - blockIdx.x;
    int q0 = qt * 64;
    int tid = threadIdx.x;
    int warp = tid >> 5, lane = tid & 31;

    const float* Qg = g_q + ((size_t)bh * T_ + q0) * HD_;
    const float* Kg = g_k + (size_t)bh * T_ * HD_;
    const float* Vg = g_v + (size_t)bh * T_ * HD_;

    #pragma unroll
    for (int i = 0; i < 4; i++) {
        int idx = (tid + i * 256) * 4;
        int r = idx >> 6, d = idx & 63;
        *reinterpret_cast<float4*>(&Qs[r * 64 + d]) =
            *reinterpret_cast<const float4*>(&Qg[r * 64 + d]);
    }

    float m_i[8], l_i[8], Oc[8][2];
    #pragma unroll
    for (int rr = 0; rr < 8; rr++) {
        m_i[rr] = -INFINITY; l_i[rr] = 0.f; Oc[rr][0] = 0.f; Oc[rr][1] = 0.f;
    }

    __syncthreads();

    int row0 = warp * 8;
    const float scale = 0.125f;

    for (int kt = 0; kt <= qt; kt++) {
        int k0 = kt * 64;

        #pragma unroll
        for (int i = 0; i < 4; i++) {
            int idx = (tid + i * 256) * 4;
            int r = idx >> 6, d = idx & 63;
            *reinterpret_cast<float4*>(&Ks[r * 68 + d]) =
                *reinterpret_cast<const float4*>(&Kg[(size_t)(k0 + r) * 64 + d]);
            *reinterpret_cast<float4*>(&Vs[r * 68 + d]) =
                *reinterpret_cast<const float4*>(&Vg[(size_t)(k0 + r) * 64 + d]);
        }
        __syncthreads();

        float s0[8], s1[8];
        #pragma unroll
        for (int rr = 0; rr < 8; rr++) { s0[rr] = 0.f; s1[rr] = 0.f; }
        #pragma unroll
        for (int d4 = 0; d4 < 16; d4++) {
            float4 kv0 = *reinterpret_cast<const float4*>(&Ks[lane * 68 + d4 * 4]);
            float4 kv1 = *reinterpret_cast<const float4*>(&Ks[(lane + 32) * 68 + d4 * 4]);
            #pragma unroll
            for (int rr = 0; rr < 8; rr++) {
                float4 qv = *reinterpret_cast<const float4*>(&Qs[(row0 + rr) * 64 + d4 * 4]);
                s0[rr] += qv.x * kv0.x + qv.y * kv0.y + qv.z * kv0.z + qv.w * kv0.w;
                s1[rr] += qv.x * kv1.x + qv.y * kv1.y + qv.z * kv1.z + qv.w * kv1.w;
            }
        }

        int key0 = k0 + lane, key1 = k0 + lane + 32;
        #pragma unroll
        for (int rr = 0; rr < 8; rr++) {
            int qidx = q0 + row0 + rr;
            float v0 = (key0 <= qidx) ? s0[rr] * scale : -INFINITY;
            float v1 = (key1 <= qidx) ? s1[rr] * scale : -INFINITY;
            float mt = fmaxf(v0, v1);
            #pragma unroll
            for (int off = 16; off > 0; off >>= 1)
                mt = fmaxf(mt, __shfl_xor_sync(0xffffffffu, mt, off));
            float mnew = fmaxf(m_i[rr], mt);
            float alpha = __expf(m_i[rr] - mnew);
            float p0 = __expf(v0 - mnew);
            float p1 = __expf(v1 - mnew);
            float rs = p0 + p1;
            #pragma unroll
            for (int off = 16; off > 0; off >>= 1)
                rs += __shfl_xor_sync(0xffffffffu, rs, off);
            l_i[rr] = l_i[rr] * alpha + rs;
            m_i[rr] = mnew;
            Oc[rr][0] *= alpha;
            Oc[rr][1] *= alpha;
            Ps[(row0 + rr) * 64 + lane]      = p0;
            Ps[(row0 + rr) * 64 + lane + 32] = p1;
        }
        __syncwarp();

        #pragma unroll
        for (int k4 = 0; k4 < 16; k4++) {
            float va[4], vb[4];
            #pragma unroll
            for (int i = 0; i < 4; i++) {
                va[i] = Vs[(k4 * 4 + i) * 68 + lane];
                vb[i] = Vs[(k4 * 4 + i) * 68 + lane + 32];
            }
            #pragma unroll
            for (int rr = 0; rr < 8; rr++) {
                float4 p = *reinterpret_cast<const float4*>(&Ps[(row0 + rr) * 64 + k4 * 4]);
                Oc[rr][0] += p.x * va[0] + p.y * va[1] + p.z * va[2] + p.w * va[3];
                Oc[rr][1] += p.x * vb[0] + p.y * vb[1] + p.z * vb[2] + p.w * vb[3];
            }
        }
        __syncthreads();
    }

    int b = bh / NH_, h = bh % NH_;
    #pragma unroll
    for (int rr = 0; rr < 8; rr++) {
        int t = q0 + row0 + rr;
        float inv = 1.f / l_i[rr];
        float* yrow = g_y + ((size_t)b * T_ + t) * C_ + h * HD_;
        yrow[lane]      = Oc[rr][0] * inv;
        yrow[lane + 32] = Oc[rr][1] * inv;
    }
}

// ---------------------------------------------------------------------------
extern "C" void kernel_launch(void* const* d_in, const int* in_sizes, int n_in,
                              void* d_out, int out_size)
{
    const float* x     = (const float*)d_in[0];
    const float* Wqkv  = (const float*)d_in[1];
    const float* bqkv  = (const float*)d_in[2];
    const float* Wproj = (const float*)d_in[3];
    const float* bproj = (const float*)d_in[4];
    float* out = (float*)d_out;

    // 1) QKV GEMM (tensor cores, bf16x3): [8192,1024]@[1024,3072] -> g_q/g_k/g_v
    {
        dim3 grid(3072 / 128, 8192 / 128);
        gemm_bf16x3<0><<<grid, 256>>>(x, Wqkv, bqkv, nullptr, M_, 3 * C_, C_);
    }

    // 2) Flash attention (causal, fp32), writes g_y
    {
        const int smem = (64 * 64 + 2 * 64 * 68 + 64 * 64) * (int)sizeof(float); // 67584
        cudaFuncSetAttribute(flash_kernel, cudaFuncAttributeMaxDynamicSharedMemorySize, smem);
        flash_kernel<<<dim3(32, 64), 256, smem>>>();
    }

    // 3) Projection GEMM (tensor cores, bf16x3): g_y@[1024,1024]+bproj -> out
    {
        dim3 grid(1024 / 128, 8192 / 128);
        gemm_bf16x3<1><<<grid, 256>>>(nullptr, Wproj, bproj, out, M_, C_, C_);
    }
}

// round 4
// speedup vs baseline: 2.9424x; 1.8439x over previous
#include <cuda_runtime.h>
#include <cuda_bf16.h>
#include <math.h>
#include <stdint.h>

// Problem constants
#define B_  4
#define T_  2048
#define C_  1024
#define NH_ 16
#define HD_ 64
#define BH_ (B_*NH_)     // 64
#define M_  (B_*T_)      // 8192

// Scratch (allocation-free): Q/K/V as bf16 hi/lo split pairs, [B,NH,T,HD]
__device__ __nv_bfloat16 g_qh[BH_*T_*HD_], g_ql[BH_*T_*HD_];
__device__ __nv_bfloat16 g_kh[BH_*T_*HD_], g_kl[BH_*T_*HD_];
__device__ __nv_bfloat16 g_vh[BH_*T_*HD_], g_vl[BH_*T_*HD_];
__device__ float g_y[M_*C_];        // [B,T,C] attention output

__device__ __forceinline__ uint32_t smem_u32(const void* p) {
    return (uint32_t)__cvta_generic_to_shared(p);
}

#define LDSM4(R, ptr)                                                          \
    asm volatile("ldmatrix.sync.aligned.m8n8.x4.shared.b16 {%0,%1,%2,%3}, [%4];" \
                 : "=r"((R)[0]), "=r"((R)[1]), "=r"((R)[2]), "=r"((R)[3])      \
                 : "r"(smem_u32(ptr)))

#define LDSM4T(R, ptr)                                                         \
    asm volatile("ldmatrix.sync.aligned.m8n8.x4.trans.shared.b16 {%0,%1,%2,%3}, [%4];" \
                 : "=r"((R)[0]), "=r"((R)[1]), "=r"((R)[2]), "=r"((R)[3])      \
                 : "r"(smem_u32(ptr)))

#define MMA16816(D, A, b0, b1)                                                 \
    asm volatile("mma.sync.aligned.m16n8k16.row.col.f32.bf16.bf16.f32 "        \
                 "{%0,%1,%2,%3}, {%4,%5,%6,%7}, {%8,%9}, {%0,%1,%2,%3};"       \
                 : "+f"((D)[0]), "+f"((D)[1]), "+f"((D)[2]), "+f"((D)[3])      \
                 : "r"((A)[0]), "r"((A)[1]), "r"((A)[2]), "r"((A)[3]),         \
                   "r"(b0), "r"(b1))

__device__ __forceinline__ void split_bf16(float x, __nv_bfloat16& h, __nv_bfloat16& l) {
    h = __float2bfloat16(x);
    l = __float2bfloat16(x - __bfloat162float(h));
}

__device__ __forceinline__ uint32_t pack2(float a, float b) {
    __nv_bfloat162 t = __halves2bfloat162(__float2bfloat16(a), __float2bfloat16(b));
    return *reinterpret_cast<uint32_t*>(&t);
}

// ---------------------------------------------------------------------------
// GEMM via 3x bf16-split tensor-core mma: C = A @ W + bias (fp32 in).
// MODE 0: A = x, scatter bf16 hi/lo into g_{q,k,v}{h,l}.
// MODE 1: A = g_y, fp32 row-major output.
// ---------------------------------------------------------------------------
template <int MODE>
__global__ __launch_bounds__(256) void gemm_bf16x3(
    const float* __restrict__ A_in, const float* __restrict__ W,
    const float* __restrict__ bias, float* __restrict__ Cout,
    int M, int N, int K)
{
    constexpr int LDA = 40;
    constexpr int LDB = 136;
    __shared__ __nv_bfloat16 Ah[128 * LDA], Al[128 * LDA];  // [m][k]
    __shared__ __nv_bfloat16 Bh[32 * LDB],  Bl[32 * LDB];   // [k][n]

    const float* A = (MODE == 0) ? A_in : g_y;

    int tid  = threadIdx.x;
    int lane = tid & 31, warp = tid >> 5;
    int cRow = blockIdx.y, cCol = blockIdx.x;
    int warpM = warp & 3, warpN = warp >> 2;
    int mr0 = warpM * 32;
    int n0w = warpN * 64;

    float acc[2][8][4];
    #pragma unroll
    for (int i = 0; i < 2; i++)
        #pragma unroll
        for (int j = 0; j < 8; j++)
            #pragma unroll
            for (int q = 0; q < 4; q++) acc[i][j][q] = 0.f;

    const float* Ab = A + (size_t)cRow * 128 * K;
    const float* Wb = W + cCol * 128;

    for (int k0 = 0; k0 < K; k0 += 32) {
        #pragma unroll
        for (int p = 0; p < 4; p++) {
            int idx = p * 256 + tid;
            int r = idx >> 3;
            int c4 = (idx & 7) << 2;
            float4 v = *reinterpret_cast<const float4*>(Ab + (size_t)r * K + k0 + c4);
            __nv_bfloat16 h0, l0, h1, l1, h2, l2, h3, l3;
            split_bf16(v.x, h0, l0); split_bf16(v.y, h1, l1);
            split_bf16(v.z, h2, l2); split_bf16(v.w, h3, l3);
            __nv_bfloat16* ah = &Ah[r * LDA + c4];
            __nv_bfloat16* al = &Al[r * LDA + c4];
            *reinterpret_cast<__nv_bfloat162*>(ah)     = __halves2bfloat162(h0, h1);
            *reinterpret_cast<__nv_bfloat162*>(ah + 2) = __halves2bfloat162(h2, h3);
            *reinterpret_cast<__nv_bfloat162*>(al)     = __halves2bfloat162(l0, l1);
            *reinterpret_cast<__nv_bfloat162*>(al + 2) = __halves2bfloat162(l2, l3);
        }
        #pragma unroll
        for (int p = 0; p < 4; p++) {
            int idx = p * 256 + tid;
            int kr = idx >> 5;
            int n4 = (idx & 31) << 2;
            float4 v = *reinterpret_cast<const float4*>(Wb + (size_t)(k0 + kr) * N + n4);
            __nv_bfloat16 h0, l0, h1, l1, h2, l2, h3, l3;
            split_bf16(v.x, h0, l0); split_bf16(v.y, h1, l1);
            split_bf16(v.z, h2, l2); split_bf16(v.w, h3, l3);
            __nv_bfloat16* bh = &Bh[kr * LDB + n4];
            __nv_bfloat16* bl = &Bl[kr * LDB + n4];
            *reinterpret_cast<__nv_bfloat162*>(bh)     = __halves2bfloat162(h0, h1);
            *reinterpret_cast<__nv_bfloat162*>(bh + 2) = __halves2bfloat162(h2, h3);
            *reinterpret_cast<__nv_bfloat162*>(bl)     = __halves2bfloat162(l0, l1);
            *reinterpret_cast<__nv_bfloat162*>(bl + 2) = __halves2bfloat162(l2, l3);
        }
        __syncthreads();

        #pragma unroll
        for (int k16 = 0; k16 < 2; k16++) {
            int kk = k16 * 16;
            uint32_t ahf[2][4], alf[2][4], bhf[4][4], blf[4][4];

            #pragma unroll
            for (int mi = 0; mi < 2; mi++) {
                int off = (mr0 + mi * 16 + (lane & 15)) * LDA + kk + ((lane >> 4) << 3);
                LDSM4(ahf[mi], &Ah[off]);
                LDSM4(alf[mi], &Al[off]);
            }
            #pragma unroll
            for (int g = 0; g < 4; g++) {
                int r = kk + ((lane & 16) >> 1) + (lane & 7);
                int c = n0w + g * 16 + (lane & 8);
                int off = r * LDB + c;
                LDSM4T(bhf[g], &Bh[off]);
                LDSM4T(blf[g], &Bl[off]);
            }

            #pragma unroll
            for (int mi = 0; mi < 2; mi++) {
                #pragma unroll
                for (int nj = 0; nj < 8; nj++) {
                    int g = nj >> 1, h = nj & 1;
                    uint32_t b0h = h ? bhf[g][1] : bhf[g][0];
                    uint32_t b1h = h ? bhf[g][3] : bhf[g][2];
                    uint32_t b0l = h ? blf[g][1] : blf[g][0];
                    uint32_t b1l = h ? blf[g][3] : blf[g][2];
                    MMA16816(acc[mi][nj], ahf[mi], b0h, b1h);
                    MMA16816(acc[mi][nj], ahf[mi], b0l, b1l);
                    MMA16816(acc[mi][nj], alf[mi], b0h, b1h);
                }
            }
        }
        __syncthreads();
    }

    int rbase = cRow * 128 + mr0 + (lane >> 2);
    int cbase = cCol * 128 + n0w + ((lane & 3) << 1);

    #pragma unroll
    for (int mi = 0; mi < 2; mi++) {
        #pragma unroll
        for (int nj = 0; nj < 8; nj++) {
            int m0 = rbase + mi * 16;
            int n  = cbase + nj * 8;
            float bv0 = bias[n], bv1 = bias[n + 1];
            float v00 = acc[mi][nj][0] + bv0, v01 = acc[mi][nj][1] + bv1;
            float v10 = acc[mi][nj][2] + bv0, v11 = acc[mi][nj][3] + bv1;
            if (MODE == 1) {
                *reinterpret_cast<float2*>(&Cout[(size_t)m0 * N + n])       = make_float2(v00, v01);
                *reinterpret_cast<float2*>(&Cout[(size_t)(m0 + 8) * N + n]) = make_float2(v10, v11);
            } else {
                int which = n / C_;
                int c = n - which * C_;
                int h = c >> 6, d = c & 63;
                __nv_bfloat16* dh = (which == 0) ? g_qh : (which == 1) ? g_kh : g_vh;
                __nv_bfloat16* dl = (which == 0) ? g_ql : (which == 1) ? g_kl : g_vl;
                int b0i = m0 >> 11, t0 = m0 & 2047;
                int b1i = (m0 + 8) >> 11, t1 = (m0 + 8) & 2047;
                size_t i0 = (((size_t)b0i * NH_ + h) * T_ + t0) * HD_ + d;
                size_t i1 = (((size_t)b1i * NH_ + h) * T_ + t1) * HD_ + d;
                __nv_bfloat16 h00, l00, h01, l01, h10, l10, h11, l11;
                split_bf16(v00, h00, l00); split_bf16(v01, h01, l01);
                split_bf16(v10, h10, l10); split_bf16(v11, h11, l11);
                *reinterpret_cast<__nv_bfloat162*>(&dh[i0]) = __halves2bfloat162(h00, h01);
                *reinterpret_cast<__nv_bfloat162*>(&dl[i0]) = __halves2bfloat162(l00, l01);
                *reinterpret_cast<__nv_bfloat162*>(&dh[i1]) = __halves2bfloat162(h10, h11);
                *reinterpret_cast<__nv_bfloat162*>(&dl[i1]) = __halves2bfloat162(l10, l11);
            }
        }
    }
}

// ---------------------------------------------------------------------------
// Flash attention via tensor cores, causal. CTA: 128 q-rows, 64-key iters.
// 8 warps x 16 rows. bf16x3 split for S = QK^T and O += P V.
// ---------------------------------------------------------------------------
__global__ __launch_bounds__(256) void flash_mma_kernel()
{
    constexpr int LDS_ = 72;   // smem row stride in bf16 (64 + 8 pad)
    extern __shared__ __nv_bfloat16 smf[];
    __nv_bfloat16* Qh = smf;                 // [128][72]
    __nv_bfloat16* Ql = Qh + 128 * LDS_;
    __nv_bfloat16* Kh = Ql + 128 * LDS_;     // [64][72]
    __nv_bfloat16* Kl = Kh + 64 * LDS_;
    __nv_bfloat16* Vh = Kl + 64 * LDS_;
    __nv_bfloat16* Vl = Vh + 64 * LDS_;

    int bh = blockIdx.y;
    int qt = gridDim.x - 1 - blockIdx.x;     // heavy q-tiles first
    int q0 = qt * 128;
    int tid = threadIdx.x;
    int warp = tid >> 5, lane = tid & 31;
    int wrow = warp * 16;
    int g = lane >> 2, t2 = (lane & 3) << 1;

    const __nv_bfloat16* Qgh = g_qh + ((size_t)bh * T_ + q0) * HD_;
    const __nv_bfloat16* Qgl = g_ql + ((size_t)bh * T_ + q0) * HD_;

    // Load Q tile hi/lo (8192 bf16 each)
    #pragma unroll
    for (int i = 0; i < 4; i++) {
        int idx = (tid + i * 256) * 8;
        int r = idx >> 6, c = idx & 63;
        *reinterpret_cast<uint4*>(&Qh[r * LDS_ + c]) =
            *reinterpret_cast<const uint4*>(&Qgh[r * 64 + c]);
        *reinterpret_cast<uint4*>(&Ql[r * LDS_ + c]) =
            *reinterpret_cast<const uint4*>(&Qgl[r * 64 + c]);
    }

    float O[8][4];
    #pragma unroll
    for (int i = 0; i < 8; i++)
        #pragma unroll
        for (int q = 0; q < 4; q++) O[i][q] = 0.f;
    float m0 = -INFINITY, m1 = -INFINITY, l0 = 0.f, l1 = 0.f;

    const float scale = 0.125f;   // 1/sqrt(64)
    int row0 = q0 + wrow + g;     // abs q row for c0/c1
    int row1 = row0 + 8;          // abs q row for c2/c3

    __syncthreads();

    int kt_max = 2 * qt + 1;
    for (int kt = 0; kt <= kt_max; kt++) {
        int k0 = kt * 64;

        // Load K/V tiles hi/lo (4096 bf16 each)
        {
            const __nv_bfloat16* kgh = g_kh + ((size_t)bh * T_ + k0) * HD_;
            const __nv_bfloat16* kgl = g_kl + ((size_t)bh * T_ + k0) * HD_;
            const __nv_bfloat16* vgh = g_vh + ((size_t)bh * T_ + k0) * HD_;
            const __nv_bfloat16* vgl = g_vl + ((size_t)bh * T_ + k0) * HD_;
            #pragma unroll
            for (int i = 0; i < 2; i++) {
                int idx = (tid + i * 256) * 8;
                int r = idx >> 6, c = idx & 63;
                *reinterpret_cast<uint4*>(&Kh[r * LDS_ + c]) = *reinterpret_cast<const uint4*>(&kgh[r * 64 + c]);
                *reinterpret_cast<uint4*>(&Kl[r * LDS_ + c]) = *reinterpret_cast<const uint4*>(&kgl[r * 64 + c]);
                *reinterpret_cast<uint4*>(&Vh[r * LDS_ + c]) = *reinterpret_cast<const uint4*>(&vgh[r * 64 + c]);
                *reinterpret_cast<uint4*>(&Vl[r * LDS_ + c]) = *reinterpret_cast<const uint4*>(&vgl[r * 64 + c]);
            }
        }
        __syncthreads();

        // ---- S = Q K^T (bf16x3) ----
        float S[8][4];
        #pragma unroll
        for (int j = 0; j < 8; j++)
            #pragma unroll
            for (int q = 0; q < 4; q++) S[j][q] = 0.f;

        #pragma unroll
        for (int ks = 0; ks < 4; ks++) {
            int kk = ks * 16;
            uint32_t qhf[4], qlf[4];
            {
                int off = (wrow + (lane & 15)) * LDS_ + kk + ((lane >> 4) << 3);
                LDSM4(qhf, &Qh[off]);
                LDSM4(qlf, &Ql[off]);
            }
            uint32_t bKh[8][2], bKl[8][2];
            #pragma unroll
            for (int tp = 0; tp < 4; tp++) {
                uint32_t R[4];
                int off = (tp * 16 + (lane & 7) + ((lane >> 4) << 3)) * LDS_
                          + kk + (((lane >> 3) & 1) << 3);
                LDSM4(R, &Kh[off]);
                bKh[2*tp][0] = R[0]; bKh[2*tp][1] = R[1];
                bKh[2*tp+1][0] = R[2]; bKh[2*tp+1][1] = R[3];
                LDSM4(R, &Kl[off]);
                bKl[2*tp][0] = R[0]; bKl[2*tp][1] = R[1];
                bKl[2*tp+1][0] = R[2]; bKl[2*tp+1][1] = R[3];
            }
            #pragma unroll
            for (int j = 0; j < 8; j++) {
                MMA16816(S[j], qhf, bKh[j][0], bKh[j][1]);
                MMA16816(S[j], qlf, bKh[j][0], bKh[j][1]);
                MMA16816(S[j], qhf, bKl[j][0], bKl[j][1]);
            }
        }

        // ---- causal mask (diagonal iters only) ----
        if (kt >= 2 * qt) {
            #pragma unroll
            for (int j = 0; j < 8; j++) {
                int key = k0 + j * 8 + t2;
                if (key     > row0) S[j][0] = -1e30f;
                if (key + 1 > row0) S[j][1] = -1e30f;
                if (key     > row1) S[j][2] = -1e30f;
                if (key + 1 > row1) S[j][3] = -1e30f;
            }
        }

        // ---- online softmax ----
        float mx0 = -1e30f, mx1 = -1e30f;
        #pragma unroll
        for (int j = 0; j < 8; j++) {
            mx0 = fmaxf(mx0, fmaxf(S[j][0], S[j][1]));
            mx1 = fmaxf(mx1, fmaxf(S[j][2], S[j][3]));
        }
        #pragma unroll
        for (int off = 1; off <= 2; off <<= 1) {
            mx0 = fmaxf(mx0, __shfl_xor_sync(0xffffffffu, mx0, off));
            mx1 = fmaxf(mx1, __shfl_xor_sync(0xffffffffu, mx1, off));
        }
        float mn0 = fmaxf(m0, mx0 * scale);
        float mn1 = fmaxf(m1, mx1 * scale);
        float a0 = __expf(m0 - mn0);
        float a1 = __expf(m1 - mn1);
        m0 = mn0; m1 = mn1;

        float s0 = 0.f, s1 = 0.f;
        #pragma unroll
        for (int j = 0; j < 8; j++) {
            S[j][0] = __expf(fmaf(S[j][0], scale, -mn0));
            S[j][1] = __expf(fmaf(S[j][1], scale, -mn0));
            S[j][2] = __expf(fmaf(S[j][2], scale, -mn1));
            S[j][3] = __expf(fmaf(S[j][3], scale, -mn1));
            s0 += S[j][0] + S[j][1];
            s1 += S[j][2] + S[j][3];
        }
        #pragma unroll
        for (int off = 1; off <= 2; off <<= 1) {
            s0 += __shfl_xor_sync(0xffffffffu, s0, off);
            s1 += __shfl_xor_sync(0xffffffffu, s1, off);
        }
        l0 = l0 * a0 + s0;
        l1 = l1 * a1 + s1;
        #pragma unroll
        for (int i = 0; i < 8; i++) {
            O[i][0] *= a0; O[i][1] *= a0;
            O[i][2] *= a1; O[i][3] *= a1;
        }

        // ---- O += P V (bf16x3) ----
        #pragma unroll
        for (int ks = 0; ks < 4; ks++) {
            int j0 = 2 * ks, j1 = 2 * ks + 1;
            uint32_t aPh[4], aPl[4];
            aPh[0] = pack2(S[j0][0], S[j0][1]);
            aPh[1] = pack2(S[j0][2], S[j0][3]);
            aPh[2] = pack2(S[j1][0], S[j1][1]);
            aPh[3] = pack2(S[j1][2], S[j1][3]);
            {
                __nv_bfloat162 h;
                h = *reinterpret_cast<__nv_bfloat162*>(&aPh[0]);
                aPl[0] = pack2(S[j0][0] - __low2float(h), S[j0][1] - __high2float(h));
                h = *reinterpret_cast<__nv_bfloat162*>(&aPh[1]);
                aPl[1] = pack2(S[j0][2] - __low2float(h), S[j0][3] - __high2float(h));
                h = *reinterpret_cast<__nv_bfloat162*>(&aPh[2]);
                aPl[2] = pack2(S[j1][0] - __low2float(h), S[j1][1] - __high2float(h));
                h = *reinterpret_cast<__nv_bfloat162*>(&aPh[3]);
                aPl[3] = pack2(S[j1][2] - __low2float(h), S[j1][3] - __high2float(h));
            }
            #pragma unroll
            for (int gd = 0; gd < 4; gd++) {
                int off = (ks * 16 + ((lane & 16) >> 1) + (lane & 7)) * LDS_
                          + gd * 16 + (lane & 8);
                uint32_t Rh[4], Rl[4];
                LDSM4T(Rh, &Vh[off]);
                LDSM4T(Rl, &Vl[off]);
                MMA16816(O[gd*2+0], aPh, Rh[0], Rh[2]);
                MMA16816(O[gd*2+1], aPh, Rh[1], Rh[3]);
                MMA16816(O[gd*2+0], aPl, Rh[0], Rh[2]);
                MMA16816(O[gd*2+1], aPl, Rh[1], Rh[3]);
                MMA16816(O[gd*2+0], aPh, Rl[0], Rl[2]);
                MMA16816(O[gd*2+1], aPh, Rl[1], Rl[3]);
            }
        }
        __syncthreads();   // before next K/V overwrite
    }

    // ---- normalize & write y [B,T,C] ----
    int b = bh >> 4, h = bh & 15;
    float inv0 = 1.f / l0, inv1 = 1.f / l1;
    float* y0 = g_y + ((size_t)b * T_ + row0) * C_ + h * 64 + t2;
    float* y1 = g_y + ((size_t)b * T_ + row1) * C_ + h * 64 + t2;
    #pragma unroll
    for (int i = 0; i < 8; i++) {
        *reinterpret_cast<float2*>(y0 + i * 8) = make_float2(O[i][0] * inv0, O[i][1] * inv0);
        *reinterpret_cast<float2*>(y1 + i * 8) = make_float2(O[i][2] * inv1, O[i][3] * inv1);
    }
}

// ---------------------------------------------------------------------------
extern "C" void kernel_launch(void* const* d_in, const int* in_sizes, int n_in,
                              void* d_out, int out_size)
{
    const float* x     = (const float*)d_in[0];
    const float* Wqkv  = (const float*)d_in[1];
    const float* bqkv  = (const float*)d_in[2];
    const float* Wproj = (const float*)d_in[3];
    const float* bproj = (const float*)d_in[4];
    float* out = (float*)d_out;

    // 1) QKV GEMM -> bf16 hi/lo Q,K,V
    {
        dim3 grid(3072 / 128, 8192 / 128);
        gemm_bf16x3<0><<<grid, 256>>>(x, Wqkv, bqkv, nullptr, M_, 3 * C_, C_);
    }

    // 2) Flash attention (tensor cores), writes g_y
    {
        const int smem = (2 * 128 * 72 + 4 * 64 * 72) * (int)sizeof(__nv_bfloat16); // 73728
        cudaFuncSetAttribute(flash_mma_kernel, cudaFuncAttributeMaxDynamicSharedMemorySize, smem);
        flash_mma_kernel<<<dim3(16, 64), 256, smem>>>();
    }

    // 3) Projection GEMM: g_y @ Wproj + bproj -> out
    {
        dim3 grid(1024 / 128, 8192 / 128);
        gemm_bf16x3<1><<<grid, 256>>>(nullptr, Wproj, bproj, out, M_, C_, C_);
    }
}

// round 5
// speedup vs baseline: 3.0095x; 1.0228x over previous
#include <cuda_runtime.h>
#include <cuda_bf16.h>
#include <math.h>
#include <stdint.h>

// Problem constants
#define B_  4
#define T_  2048
#define C_  1024
#define NH_ 16
#define HD_ 64
#define BH_ (B_*NH_)     // 64
#define M_  (B_*T_)      // 8192

// Scratch (allocation-free device globals), all bf16 hi/lo split pairs
__device__ __nv_bfloat16 g_xh[M_*C_],      g_xl[M_*C_];        // x split
__device__ __nv_bfloat16 g_wqkvh[C_*3*C_], g_wqkvl[C_*3*C_];   // Wqkv split
__device__ __nv_bfloat16 g_wph[C_*C_],     g_wpl[C_*C_];       // Wproj split
__device__ __nv_bfloat16 g_qh[BH_*T_*HD_], g_ql[BH_*T_*HD_];   // [B,NH,T,HD]
__device__ __nv_bfloat16 g_kh[BH_*T_*HD_], g_kl[BH_*T_*HD_];
__device__ __nv_bfloat16 g_vh[BH_*T_*HD_], g_vl[BH_*T_*HD_];
__device__ __nv_bfloat16 g_yh[M_*C_],      g_yl[M_*C_];        // attention out split

__device__ __forceinline__ uint32_t smem_u32(const void* p) {
    return (uint32_t)__cvta_generic_to_shared(p);
}

#define LDSM4(R, ptr)                                                          \
    asm volatile("ldmatrix.sync.aligned.m8n8.x4.shared.b16 {%0,%1,%2,%3}, [%4];" \
                 : "=r"((R)[0]), "=r"((R)[1]), "=r"((R)[2]), "=r"((R)[3])      \
                 : "r"(smem_u32(ptr)))

#define LDSM4T(R, ptr)                                                         \
    asm volatile("ldmatrix.sync.aligned.m8n8.x4.trans.shared.b16 {%0,%1,%2,%3}, [%4];" \
                 : "=r"((R)[0]), "=r"((R)[1]), "=r"((R)[2]), "=r"((R)[3])      \
                 : "r"(smem_u32(ptr)))

#define MMA16816(D, A, b0, b1)                                                 \
    asm volatile("mma.sync.aligned.m16n8k16.row.col.f32.bf16.bf16.f32 "        \
                 "{%0,%1,%2,%3}, {%4,%5,%6,%7}, {%8,%9}, {%0,%1,%2,%3};"       \
                 : "+f"((D)[0]), "+f"((D)[1]), "+f"((D)[2]), "+f"((D)[3])      \
                 : "r"((A)[0]), "r"((A)[1]), "r"((A)[2]), "r"((A)[3]),         \
                   "r"(b0), "r"(b1))

__device__ __forceinline__ void cp16(uint32_t dst, const void* src) {
    asm volatile("cp.async.cg.shared.global [%0], [%1], 16;" :: "r"(dst), "l"(src));
}
#define CP_COMMIT() asm volatile("cp.async.commit_group;")
#define CP_WAIT0()  asm volatile("cp.async.wait_group 0;")

__device__ __forceinline__ void split_bf16(float x, __nv_bfloat16& h, __nv_bfloat16& l) {
    h = __float2bfloat16(x);
    l = __float2bfloat16(x - __bfloat162float(h));
}

__device__ __forceinline__ uint32_t pack2(float a, float b) {
    __nv_bfloat162 t = __halves2bfloat162(__float2bfloat16(a), __float2bfloat16(b));
    return *reinterpret_cast<uint32_t*>(&t);
}

// ---------------------------------------------------------------------------
// Elementwise fp32 -> bf16 hi/lo split
// ---------------------------------------------------------------------------
__global__ __launch_bounds__(256) void split_pass(
    const float* __restrict__ in, __nv_bfloat16* __restrict__ oh,
    __nv_bfloat16* __restrict__ ol, int n4)
{
    int i = blockIdx.x * blockDim.x + threadIdx.x;
    if (i >= n4) return;
    float4 v = reinterpret_cast<const float4*>(in)[i];
    __nv_bfloat16 h0, l0, h1, l1, h2, l2, h3, l3;
    split_bf16(v.x, h0, l0); split_bf16(v.y, h1, l1);
    split_bf16(v.z, h2, l2); split_bf16(v.w, h3, l3);
    reinterpret_cast<__nv_bfloat162*>(oh)[2*i]   = __halves2bfloat162(h0, h1);
    reinterpret_cast<__nv_bfloat162*>(oh)[2*i+1] = __halves2bfloat162(h2, h3);
    reinterpret_cast<__nv_bfloat162*>(ol)[2*i]   = __halves2bfloat162(l0, l1);
    reinterpret_cast<__nv_bfloat162*>(ol)[2*i+1] = __halves2bfloat162(l2, l3);
}

// ---------------------------------------------------------------------------
// GEMM on pre-split bf16 hi/lo operands, cp.async 2-stage pipeline.
// Block 128x128, BK=32, 256 threads = 8 warps (4m x 2n), 3-MMA bf16x3 scheme.
// MODE 0: A = g_x{h,l}, W = g_wqkv{h,l}; scatter into g_{q,k,v}{h,l}.
// MODE 1: A = g_y{h,l}, W = g_wp{h,l};  fp32 row-major output + bias.
// ---------------------------------------------------------------------------
template <int MODE>
__global__ __launch_bounds__(256) void gemm_pre(
    const float* __restrict__ bias, float* __restrict__ Cout, int M, int N, int K)
{
    constexpr int LDA = 40;    // A smem stride (32+8), bf16
    constexpr int LDB = 136;   // B smem stride (128+8), bf16
    constexpr int ASZ = 128 * LDA;          // 5120 elems
    constexpr int BSZ = 32 * LDB;           // 4352 elems
    constexpr int STAGE = 2 * ASZ + 2 * BSZ; // 18944 elems per stage

    extern __shared__ __nv_bfloat16 smem[];

    const __nv_bfloat16* Agh = (MODE == 0) ? g_xh : g_yh;
    const __nv_bfloat16* Agl = (MODE == 0) ? g_xl : g_yl;
    const __nv_bfloat16* Wgh = (MODE == 0) ? g_wqkvh : g_wph;
    const __nv_bfloat16* Wgl = (MODE == 0) ? g_wqkvl : g_wpl;

    int tid  = threadIdx.x;
    int lane = tid & 31, warp = tid >> 5;
    int cRow = blockIdx.y, cCol = blockIdx.x;
    int warpM = warp & 3, warpN = warp >> 2;
    int mr0 = warpM * 32;
    int n0w = warpN * 64;

    const __nv_bfloat16* Abh = Agh + (size_t)cRow * 128 * K;
    const __nv_bfloat16* Abl = Agl + (size_t)cRow * 128 * K;
    const __nv_bfloat16* Wbh = Wgh + cCol * 128;
    const __nv_bfloat16* Wbl = Wgl + cCol * 128;

    // per-thread copy coordinates
    int ar0 = tid >> 2,  aq0 = (tid & 3) << 3;              // A chunk 0: rows 0..63
    int ar1 = ar0 + 64;                                     // A chunk 1
    int br0 = tid >> 4,  bq0 = (tid & 15) << 3;             // B chunk 0: rows 0..15
    int br1 = br0 + 16;                                     // B chunk 1

    uint32_t smem_base = smem_u32(smem);

    auto issue_stage = [&](int st, int k0) {
        uint32_t sb = smem_base + st * STAGE * 2;           // bytes
        uint32_t ah = sb, al = sb + ASZ * 2, bh = sb + 2 * ASZ * 2, bl = sb + (2 * ASZ + BSZ) * 2;
        cp16(ah + (ar0 * LDA + aq0) * 2, Abh + (size_t)ar0 * K + k0 + aq0);
        cp16(ah + (ar1 * LDA + aq0) * 2, Abh + (size_t)ar1 * K + k0 + aq0);
        cp16(al + (ar0 * LDA + aq0) * 2, Abl + (size_t)ar0 * K + k0 + aq0);
        cp16(al + (ar1 * LDA + aq0) * 2, Abl + (size_t)ar1 * K + k0 + aq0);
        cp16(bh + (br0 * LDB + bq0) * 2, Wbh + (size_t)(k0 + br0) * N + bq0);
        cp16(bh + (br1 * LDB + bq0) * 2, Wbh + (size_t)(k0 + br1) * N + bq0);
        cp16(bl + (br0 * LDB + bq0) * 2, Wbl + (size_t)(k0 + br0) * N + bq0);
        cp16(bl + (br1 * LDB + bq0) * 2, Wbl + (size_t)(k0 + br1) * N + bq0);
    };

    float acc[2][8][4];
    #pragma unroll
    for (int i = 0; i < 2; i++)
        #pragma unroll
        for (int j = 0; j < 8; j++)
            #pragma unroll
            for (int q = 0; q < 4; q++) acc[i][j][q] = 0.f;

    issue_stage(0, 0);
    CP_COMMIT();

    int NT = K / 32;
    for (int it = 0; it < NT; it++) {
        CP_WAIT0();
        __syncthreads();
        if (it + 1 < NT) {
            issue_stage((it + 1) & 1, (it + 1) * 32);
            CP_COMMIT();
        }

        __nv_bfloat16* Ah = smem + (it & 1) * STAGE;
        __nv_bfloat16* Al = Ah + ASZ;
        __nv_bfloat16* Bh = Al + ASZ;
        __nv_bfloat16* Bl = Bh + BSZ;

        #pragma unroll
        for (int k16 = 0; k16 < 2; k16++) {
            int kk = k16 * 16;
            uint32_t ahf[2][4], alf[2][4], bhf[4][4], blf[4][4];

            #pragma unroll
            for (int mi = 0; mi < 2; mi++) {
                int off = (mr0 + mi * 16 + (lane & 15)) * LDA + kk + ((lane >> 4) << 3);
                LDSM4(ahf[mi], &Ah[off]);
                LDSM4(alf[mi], &Al[off]);
            }
            #pragma unroll
            for (int g = 0; g < 4; g++) {
                int r = kk + ((lane & 16) >> 1) + (lane & 7);
                int c = n0w + g * 16 + (lane & 8);
                int off = r * LDB + c;
                LDSM4T(bhf[g], &Bh[off]);
                LDSM4T(blf[g], &Bl[off]);
            }

            #pragma unroll
            for (int mi = 0; mi < 2; mi++) {
                #pragma unroll
                for (int nj = 0; nj < 8; nj++) {
                    int g = nj >> 1, h = nj & 1;
                    uint32_t b0h = h ? bhf[g][1] : bhf[g][0];
                    uint32_t b1h = h ? bhf[g][3] : bhf[g][2];
                    uint32_t b0l = h ? blf[g][1] : blf[g][0];
                    uint32_t b1l = h ? blf[g][3] : blf[g][2];
                    MMA16816(acc[mi][nj], ahf[mi], b0h, b1h);
                    MMA16816(acc[mi][nj], ahf[mi], b0l, b1l);
                    MMA16816(acc[mi][nj], alf[mi], b0h, b1h);
                }
            }
        }
        __syncthreads();
    }

    // --- epilogue ---
    int rbase = cRow * 128 + mr0 + (lane >> 2);
    int cbase = cCol * 128 + n0w + ((lane & 3) << 1);

    #pragma unroll
    for (int mi = 0; mi < 2; mi++) {
        #pragma unroll
        for (int nj = 0; nj < 8; nj++) {
            int m0 = rbase + mi * 16;
            int n  = cbase + nj * 8;
            float bv0 = bias[n], bv1 = bias[n + 1];
            float v00 = acc[mi][nj][0] + bv0, v01 = acc[mi][nj][1] + bv1;
            float v10 = acc[mi][nj][2] + bv0, v11 = acc[mi][nj][3] + bv1;
            if (MODE == 1) {
                *reinterpret_cast<float2*>(&Cout[(size_t)m0 * N + n])       = make_float2(v00, v01);
                *reinterpret_cast<float2*>(&Cout[(size_t)(m0 + 8) * N + n]) = make_float2(v10, v11);
            } else {
                int which = n / C_;
                int c = n - which * C_;
                int h = c >> 6, d = c & 63;
                __nv_bfloat16* dh = (which == 0) ? g_qh : (which == 1) ? g_kh : g_vh;
                __nv_bfloat16* dl = (which == 0) ? g_ql : (which == 1) ? g_kl : g_vl;
                int b0i = m0 >> 11, t0 = m0 & 2047;
                int b1i = (m0 + 8) >> 11, t1 = (m0 + 8) & 2047;
                size_t i0 = (((size_t)b0i * NH_ + h) * T_ + t0) * HD_ + d;
                size_t i1 = (((size_t)b1i * NH_ + h) * T_ + t1) * HD_ + d;
                __nv_bfloat16 h00, l00, h01, l01, h10, l10, h11, l11;
                split_bf16(v00, h00, l00); split_bf16(v01, h01, l01);
                split_bf16(v10, h10, l10); split_bf16(v11, h11, l11);
                *reinterpret_cast<__nv_bfloat162*>(&dh[i0]) = __halves2bfloat162(h00, h01);
                *reinterpret_cast<__nv_bfloat162*>(&dl[i0]) = __halves2bfloat162(l00, l01);
                *reinterpret_cast<__nv_bfloat162*>(&dh[i1]) = __halves2bfloat162(h10, h11);
                *reinterpret_cast<__nv_bfloat162*>(&dl[i1]) = __halves2bfloat162(l10, l11);
            }
        }
    }
}

// ---------------------------------------------------------------------------
// Flash attention via tensor cores, causal. CTA: 128 q-rows, 64-key iters.
// 8 warps x 16 rows. bf16x3 split for S = QK^T and O += P V.
// Epilogue writes y as bf16 hi/lo split (for the pre-split proj GEMM).
// ---------------------------------------------------------------------------
__global__ __launch_bounds__(256) void flash_mma_kernel()
{
    constexpr int LDS_ = 72;
    extern __shared__ __nv_bfloat16 smf[];
    __nv_bfloat16* Qh = smf;                 // [128][72]
    __nv_bfloat16* Ql = Qh + 128 * LDS_;
    __nv_bfloat16* Kh = Ql + 128 * LDS_;     // [64][72]
    __nv_bfloat16* Kl = Kh + 64 * LDS_;
    __nv_bfloat16* Vh = Kl + 64 * LDS_;
    __nv_bfloat16* Vl = Vh + 64 * LDS_;

    int bh = blockIdx.y;
    int qt = gridDim.x - 1 - blockIdx.x;
    int q0 = qt * 128;
    int tid = threadIdx.x;
    int warp = tid >> 5, lane = tid & 31;
    int wrow = warp * 16;
    int g = lane >> 2, t2 = (lane & 3) << 1;

    const __nv_bfloat16* Qgh = g_qh + ((size_t)bh * T_ + q0) * HD_;
    const __nv_bfloat16* Qgl = g_ql + ((size_t)bh * T_ + q0) * HD_;

    #pragma unroll
    for (int i = 0; i < 4; i++) {
        int idx = (tid + i * 256) * 8;
        int r = idx >> 6, c = idx & 63;
        *reinterpret_cast<uint4*>(&Qh[r * LDS_ + c]) =
            *reinterpret_cast<const uint4*>(&Qgh[r * 64 + c]);
        *reinterpret_cast<uint4*>(&Ql[r * LDS_ + c]) =
            *reinterpret_cast<const uint4*>(&Qgl[r * 64 + c]);
    }

    float O[8][4];
    #pragma unroll
    for (int i = 0; i < 8; i++)
        #pragma unroll
        for (int q = 0; q < 4; q++) O[i][q] = 0.f;
    float m0 = -INFINITY, m1 = -INFINITY, l0 = 0.f, l1 = 0.f;

    const float scale = 0.125f;
    int row0 = q0 + wrow + g;
    int row1 = row0 + 8;

    __syncthreads();

    int kt_max = 2 * qt + 1;
    for (int kt = 0; kt <= kt_max; kt++) {
        int k0 = kt * 64;

        {
            const __nv_bfloat16* kgh = g_kh + ((size_t)bh * T_ + k0) * HD_;
            const __nv_bfloat16* kgl = g_kl + ((size_t)bh * T_ + k0) * HD_;
            const __nv_bfloat16* vgh = g_vh + ((size_t)bh * T_ + k0) * HD_;
            const __nv_bfloat16* vgl = g_vl + ((size_t)bh * T_ + k0) * HD_;
            #pragma unroll
            for (int i = 0; i < 2; i++) {
                int idx = (tid + i * 256) * 8;
                int r = idx >> 6, c = idx & 63;
                *reinterpret_cast<uint4*>(&Kh[r * LDS_ + c]) = *reinterpret_cast<const uint4*>(&kgh[r * 64 + c]);
                *reinterpret_cast<uint4*>(&Kl[r * LDS_ + c]) = *reinterpret_cast<const uint4*>(&kgl[r * 64 + c]);
                *reinterpret_cast<uint4*>(&Vh[r * LDS_ + c]) = *reinterpret_cast<const uint4*>(&vgh[r * 64 + c]);
                *reinterpret_cast<uint4*>(&Vl[r * LDS_ + c]) = *reinterpret_cast<const uint4*>(&vgl[r * 64 + c]);
            }
        }
        __syncthreads();

        float S[8][4];
        #pragma unroll
        for (int j = 0; j < 8; j++)
            #pragma unroll
            for (int q = 0; q < 4; q++) S[j][q] = 0.f;

        #pragma unroll
        for (int ks = 0; ks < 4; ks++) {
            int kk = ks * 16;
            uint32_t qhf[4], qlf[4];
            {
                int off = (wrow + (lane & 15)) * LDS_ + kk + ((lane >> 4) << 3);
                LDSM4(qhf, &Qh[off]);
                LDSM4(qlf, &Ql[off]);
            }
            uint32_t bKh[8][2], bKl[8][2];
            #pragma unroll
            for (int tp = 0; tp < 4; tp++) {
                uint32_t R[4];
                int off = (tp * 16 + (lane & 7) + ((lane >> 4) << 3)) * LDS_
                          + kk + (((lane >> 3) & 1) << 3);
                LDSM4(R, &Kh[off]);
                bKh[2*tp][0] = R[0]; bKh[2*tp][1] = R[1];
                bKh[2*tp+1][0] = R[2]; bKh[2*tp+1][1] = R[3];
                LDSM4(R, &Kl[off]);
                bKl[2*tp][0] = R[0]; bKl[2*tp][1] = R[1];
                bKl[2*tp+1][0] = R[2]; bKl[2*tp+1][1] = R[3];
            }
            #pragma unroll
            for (int j = 0; j < 8; j++) {
                MMA16816(S[j], qhf, bKh[j][0], bKh[j][1]);
                MMA16816(S[j], qlf, bKh[j][0], bKh[j][1]);
                MMA16816(S[j], qhf, bKl[j][0], bKl[j][1]);
            }
        }

        if (kt >= 2 * qt) {
            #pragma unroll
            for (int j = 0; j < 8; j++) {
                int key = k0 + j * 8 + t2;
                if (key     > row0) S[j][0] = -1e30f;
                if (key + 1 > row0) S[j][1] = -1e30f;
                if (key     > row1) S[j][2] = -1e30f;
                if (key + 1 > row1) S[j][3] = -1e30f;
            }
        }

        float mx0 = -1e30f, mx1 = -1e30f;
        #pragma unroll
        for (int j = 0; j < 8; j++) {
            mx0 = fmaxf(mx0, fmaxf(S[j][0], S[j][1]));
            mx1 = fmaxf(mx1, fmaxf(S[j][2], S[j][3]));
        }
        #pragma unroll
        for (int off = 1; off <= 2; off <<= 1) {
            mx0 = fmaxf(mx0, __shfl_xor_sync(0xffffffffu, mx0, off));
            mx1 = fmaxf(mx1, __shfl_xor_sync(0xffffffffu, mx1, off));
        }
        float mn0 = fmaxf(m0, mx0 * scale);
        float mn1 = fmaxf(m1, mx1 * scale);
        float a0 = __expf(m0 - mn0);
        float a1 = __expf(m1 - mn1);
        m0 = mn0; m1 = mn1;

        float s0 = 0.f, s1 = 0.f;
        #pragma unroll
        for (int j = 0; j < 8; j++) {
            S[j][0] = __expf(fmaf(S[j][0], scale, -mn0));
            S[j][1] = __expf(fmaf(S[j][1], scale, -mn0));
            S[j][2] = __expf(fmaf(S[j][2], scale, -mn1));
            S[j][3] = __expf(fmaf(S[j][3], scale, -mn1));
            s0 += S[j][0] + S[j][1];
            s1 += S[j][2] + S[j][3];
        }
        #pragma unroll
        for (int off = 1; off <= 2; off <<= 1) {
            s0 += __shfl_xor_sync(0xffffffffu, s0, off);
            s1 += __shfl_xor_sync(0xffffffffu, s1, off);
        }
        l0 = l0 * a0 + s0;
        l1 = l1 * a1 + s1;
        #pragma unroll
        for (int i = 0; i < 8; i++) {
            O[i][0] *= a0; O[i][1] *= a0;
            O[i][2] *= a1; O[i][3] *= a1;
        }

        #pragma unroll
        for (int ks = 0; ks < 4; ks++) {
            int j0 = 2 * ks, j1 = 2 * ks + 1;
            uint32_t aPh[4], aPl[4];
            aPh[0] = pack2(S[j0][0], S[j0][1]);
            aPh[1] = pack2(S[j0][2], S[j0][3]);
            aPh[2] = pack2(S[j1][0], S[j1][1]);
            aPh[3] = pack2(S[j1][2], S[j1][3]);
            {
                __nv_bfloat162 h;
                h = *reinterpret_cast<__nv_bfloat162*>(&aPh[0]);
                aPl[0] = pack2(S[j0][0] - __low2float(h), S[j0][1] - __high2float(h));
                h = *reinterpret_cast<__nv_bfloat162*>(&aPh[1]);
                aPl[1] = pack2(S[j0][2] - __low2float(h), S[j0][3] - __high2float(h));
                h = *reinterpret_cast<__nv_bfloat162*>(&aPh[2]);
                aPl[2] = pack2(S[j1][0] - __low2float(h), S[j1][1] - __high2float(h));
                h = *reinterpret_cast<__nv_bfloat162*>(&aPh[3]);
                aPl[3] = pack2(S[j1][2] - __low2float(h), S[j1][3] - __high2float(h));
            }
            #pragma unroll
            for (int gd = 0; gd < 4; gd++) {
                int off = (ks * 16 + ((lane & 16) >> 1) + (lane & 7)) * LDS_
                          + gd * 16 + (lane & 8);
                uint32_t Rh[4], Rl[4];
                LDSM4T(Rh, &Vh[off]);
                LDSM4T(Rl, &Vl[off]);
                MMA16816(O[gd*2+0], aPh, Rh[0], Rh[2]);
                MMA16816(O[gd*2+1], aPh, Rh[1], Rh[3]);
                MMA16816(O[gd*2+0], aPl, Rh[0], Rh[2]);
                MMA16816(O[gd*2+1], aPl, Rh[1], Rh[3]);
                MMA16816(O[gd*2+0], aPh, Rl[0], Rl[2]);
                MMA16816(O[gd*2+1], aPh, Rl[1], Rl[3]);
            }
        }
        __syncthreads();
    }

    // ---- normalize & write y split hi/lo at [B,T,C] ----
    int b = bh >> 4, h = bh & 15;
    float inv0 = 1.f / l0, inv1 = 1.f / l1;
    size_t base0 = ((size_t)b * T_ + row0) * C_ + h * 64 + t2;
    size_t base1 = ((size_t)b * T_ + row1) * C_ + h * 64 + t2;
    #pragma unroll
    for (int i = 0; i < 8; i++) {
        float v0 = O[i][0] * inv0, v1 = O[i][1] * inv0;
        float v2 = O[i][2] * inv1, v3 = O[i][3] * inv1;
        __nv_bfloat16 h0, l0b, h1, l1b, h2, l2b, h3, l3b;
        split_bf16(v0, h0, l0b); split_bf16(v1, h1, l1b);
        split_bf16(v2, h2, l2b); split_bf16(v3, h3, l3b);
        *reinterpret_cast<__nv_bfloat162*>(&g_yh[base0 + i * 8]) = __halves2bfloat162(h0, h1);
        *reinterpret_cast<__nv_bfloat162*>(&g_yl[base0 + i * 8]) = __halves2bfloat162(l0b, l1b);
        *reinterpret_cast<__nv_bfloat162*>(&g_yh[base1 + i * 8]) = __halves2bfloat162(h2, h3);
        *reinterpret_cast<__nv_bfloat162*>(&g_yl[base1 + i * 8]) = __halves2bfloat162(l2b, l3b);
    }
}

// ---------------------------------------------------------------------------
extern "C" void kernel_launch(void* const* d_in, const int* in_sizes, int n_in,
                              void* d_out, int out_size)
{
    const float* x     = (const float*)d_in[0];
    const float* Wqkv  = (const float*)d_in[1];
    const float* bqkv  = (const float*)d_in[2];
    const float* Wproj = (const float*)d_in[3];
    const float* bproj = (const float*)d_in[4];
    float* out = (float*)d_out;

    static __nv_bfloat16 *xh_p = nullptr, *xl_p, *wqh_p, *wql_p, *wph_p, *wpl_p;
    if (!xh_p) {
        cudaGetSymbolAddress((void**)&xh_p,  g_xh);
        cudaGetSymbolAddress((void**)&xl_p,  g_xl);
        cudaGetSymbolAddress((void**)&wqh_p, g_wqkvh);
        cudaGetSymbolAddress((void**)&wql_p, g_wqkvl);
        cudaGetSymbolAddress((void**)&wph_p, g_wph);
        cudaGetSymbolAddress((void**)&wpl_p, g_wpl);
    }

    // 0) Pre-split fp32 inputs into bf16 hi/lo
    split_pass<<<(M_ * C_ / 4 + 255) / 256, 256>>>(x, xh_p, xl_p, M_ * C_ / 4);
    split_pass<<<(C_ * 3 * C_ / 4 + 255) / 256, 256>>>(Wqkv, wqh_p, wql_p, C_ * 3 * C_ / 4);
    split_pass<<<(C_ * C_ / 4 + 255) / 256, 256>>>(Wproj, wph_p, wpl_p, C_ * C_ / 4);

    const int gemm_smem = 2 * (2 * 128 * 40 + 2 * 32 * 136) * (int)sizeof(__nv_bfloat16); // 75776

    // 1) QKV GEMM -> bf16 hi/lo Q,K,V
    {
        cudaFuncSetAttribute(gemm_pre<0>, cudaFuncAttributeMaxDynamicSharedMemorySize, gemm_smem);
        dim3 grid(3072 / 128, 8192 / 128);
        gemm_pre<0><<<grid, 256, gemm_smem>>>(bqkv, nullptr, M_, 3 * C_, C_);
    }

    // 2) Flash attention (tensor cores), writes g_yh/g_yl
    {
        const int smem = (2 * 128 * 72 + 4 * 64 * 72) * (int)sizeof(__nv_bfloat16); // 73728
        cudaFuncSetAttribute(flash_mma_kernel, cudaFuncAttributeMaxDynamicSharedMemorySize, smem);
        flash_mma_kernel<<<dim3(16, 64), 256, smem>>>();
    }

    // 3) Projection GEMM: y @ Wproj + bproj -> out
    {
        cudaFuncSetAttribute(gemm_pre<1>, cudaFuncAttributeMaxDynamicSharedMemorySize, gemm_smem);
        dim3 grid(1024 / 128, 8192 / 128);
        gemm_pre<1><<<grid, 256, gemm_smem>>>(bproj, out, M_, C_, C_);
    }
}